// round 5
// baseline (speedup 1.0000x reference)
#include <cuda_runtime.h>

#define FULLMASK 0xffffffffu

__device__ __forceinline__ float2 cmul(float2 a, float2 b){
    return make_float2(a.x*b.x - a.y*b.y, a.x*b.y + a.y*b.x);
}
__device__ __forceinline__ float2 cadd(float2 a, float2 b){
    return make_float2(a.x + b.x, a.y + b.y);
}
__device__ __forceinline__ float2 cmadd(float2 acc, float2 a, float2 b){
    acc.x = fmaf(a.x, b.x, fmaf(-a.y, b.y, acc.x));
    acc.y = fmaf(a.x, b.y, fmaf( a.y, b.x, acc.y));
    return acc;
}
__device__ __forceinline__ float2 shflx(float2 v, int m){
    float2 r;
    r.x = __shfl_xor_sync(FULLMASK, v.x, m);
    r.y = __shfl_xor_sync(FULLMASK, v.y, m);
    return r;
}
__device__ __forceinline__ void gapply(float2 &a0, float2 &a1,
                                       float2 g00, float2 g01, float2 g10, float2 g11){
    float2 n0 = cadd(cmul(g00, a0), cmul(g01, a1));
    float2 n1 = cadd(cmul(g10, a0), cmul(g11, a1));
    a0 = n0; a1 = n1;
}

// One CTA per sample. 4096 amplitudes = 256 threads x 16 register-resident complex.
// Index bit layout of amplitude k = tid*16 + m:
//   bits 0..3  = m      (wires 11..8)
//   bits 4..8  = lane   (wires 7..3)
//   bits 9..11 = warp   (wires 2..0)
__global__ void __launch_bounds__(256) qsim_kernel(
    const float* __restrict__ x,        // [B,12]
    const float* __restrict__ params,   // [3,12,3]
    const float* __restrict__ hw,       // [12]
    const float* __restrict__ hb,       // [1]
    float* __restrict__ out)            // [B]
{
    __shared__ float2 ex[4096];         // 32KB exchange buffer (warp-dim transform)
    __shared__ float2 sW[3][8][8];      // per-layer 8x8 warp transform (wires 0-2 + C(0,1)+C(1,2))
    __shared__ float2 sG[3][12][4];     // fused RY*RZ*RY 2x2 gates
    __shared__ float  sC[12], sS[12], sHw[12];
    __shared__ float  sRed[8];

    const int tid  = threadIdx.x;
    const int lane = tid & 31;
    const int warp = tid >> 5;
    const int b    = blockIdx.x;

    // ---- Stage 0: gate precompute (sample-independent fused gates + per-sample RX angles)
    if (tid < 36){
        int l = tid / 12, i = tid % 12;
        float pa = params[(l*12 + i)*3 + 0];
        float pb = params[(l*12 + i)*3 + 1];
        float pc = params[(l*12 + i)*3 + 2];
        float ca, sa, cb, sb, cc, sc;
        sincosf(0.5f*pa, &sa, &ca);
        sincosf(0.5f*pb, &sb, &cb);
        sincosf(0.5f*pc, &sc, &cc);
        // g = RY(pc) * RZ(pb) * RY(pa);  em=e^{-i pb/2}, ep=conj(em)
        float2 em = make_float2(cb, -sb);
        float2 ep = make_float2(cb,  sb);
        float ccca = cc*ca, scsa = sc*sa, ccsa = cc*sa, scca = sc*ca;
        sG[l][i][0] = make_float2( ccca*em.x - scsa*ep.x,  ccca*em.y - scsa*ep.y);
        sG[l][i][1] = make_float2(-ccsa*em.x - scca*ep.x, -ccsa*em.y - scca*ep.y);
        sG[l][i][2] = make_float2( scca*em.x + ccsa*ep.x,  scca*em.y + ccsa*ep.y);
        sG[l][i][3] = make_float2(-scsa*em.x + ccca*ep.x, -scsa*em.y + ccca*ep.y);
    } else if (tid >= 64 && tid < 76){
        int i = tid - 64;
        float s, c;
        sincosf(0.5f * x[b*12 + i], &s, &c);
        sC[i] = c; sS[i] = s;
        sHw[i] = hw[i];
    }
    __syncthreads();

    // Build W_l[v][w'] = (G0 (x) G1 (x) G2)[sigma^-1(v)][w'] with the CNOT(0,1),CNOT(1,2)
    // permutations folded in.  Warp-index bits: bit2=wire0, bit1=wire1, bit0=wire2.
    if (tid < 192){
        int l = tid >> 6, r = tid & 63, v = r >> 3, wp = r & 7;
        int u = v ^ ((v >> 1) & 1);        // inverse of CNOT(1,2): ctrl bit1 -> tgt bit0
        u ^= ((u >> 2) & 1) << 1;          // inverse of CNOT(0,1): ctrl bit2 -> tgt bit1
        float2 t = cmul(sG[l][0][((u>>2)&1)*2 + ((wp>>2)&1)],
                        sG[l][1][((u>>1)&1)*2 + ((wp>>1)&1)]);
        t = cmul(t, sG[l][2][(u&1)*2 + (wp&1)]);
        sW[l][v][wp] = t;
    }
    __syncthreads();

    // ---- Init: product state after RX encoding layer (RX column 0 = [cos, -i sin])
    float2 a[16];
    {
        float2 base = make_float2(1.f, 0.f);
        #pragma unroll
        for (int i = 0; i < 8; i++){
            int v = (tid >> (7 - i)) & 1;   // wire i (0..7) lives at index bit 11-i = tid bit 7-i
            float2 f = v ? make_float2(0.f, -sS[i]) : make_float2(sC[i], 0.f);
            base = cmul(base, f);
        }
        float2 t8[2], t9[4], t10[8];
        t8[0] = make_float2(base.x*sC[8], base.y*sC[8]);
        t8[1] = cmul(base, make_float2(0.f, -sS[8]));
        #pragma unroll
        for (int u = 0; u < 2; u++){
            t9[2*u]   = make_float2(t8[u].x*sC[9], t8[u].y*sC[9]);
            t9[2*u+1] = cmul(t8[u], make_float2(0.f, -sS[9]));
        }
        #pragma unroll
        for (int u = 0; u < 4; u++){
            t10[2*u]   = make_float2(t9[u].x*sC[10], t9[u].y*sC[10]);
            t10[2*u+1] = cmul(t9[u], make_float2(0.f, -sS[10]));
        }
        #pragma unroll
        for (int u = 0; u < 8; u++){
            a[2*u]   = make_float2(t10[u].x*sC[11], t10[u].y*sC[11]);
            a[2*u+1] = cmul(t10[u], make_float2(0.f, -sS[11]));
        }
    }

    // ---- 3 layers
    for (int l = 0; l < 3; l++){
        // Local gates: wires 8..11 <-> m bits 3..0 (register only)
        {
            float2 g00=sG[l][8][0], g01=sG[l][8][1], g10=sG[l][8][2], g11=sG[l][8][3];
            #pragma unroll
            for (int m = 0; m < 8; m++) gapply(a[m], a[m+8], g00, g01, g10, g11);
        }
        {
            float2 g00=sG[l][9][0], g01=sG[l][9][1], g10=sG[l][9][2], g11=sG[l][9][3];
            #pragma unroll
            for (int m = 0; m < 16; m++) if (!(m & 4)) gapply(a[m], a[m+4], g00, g01, g10, g11);
        }
        {
            float2 g00=sG[l][10][0], g01=sG[l][10][1], g10=sG[l][10][2], g11=sG[l][10][3];
            #pragma unroll
            for (int m = 0; m < 16; m++) if (!(m & 2)) gapply(a[m], a[m+2], g00, g01, g10, g11);
        }
        {
            float2 g00=sG[l][11][0], g01=sG[l][11][1], g10=sG[l][11][2], g11=sG[l][11][3];
            #pragma unroll
            for (int m = 0; m < 16; m++) if (!(m & 1)) gapply(a[m], a[m+1], g00, g01, g10, g11);
        }

        // Lane gates: wires 3..7 <-> lane masks 16,8,4,2,1 (shuffle butterflies)
        #pragma unroll
        for (int w = 3; w < 8; w++){
            const int mask = 1 << (7 - w);
            float2 g00=sG[l][w][0], g01=sG[l][w][1], g10=sG[l][w][2], g11=sG[l][w][3];
            const bool hi = (lane & mask) != 0;
            #pragma unroll
            for (int m = 0; m < 16; m++){
                float2 o = shflx(a[m], mask);
                a[m] = hi ? cadd(cmul(g10, o), cmul(g11, a[m]))
                          : cadd(cmul(g00, a[m]), cmul(g01, o));
            }
        }

        // Warp-dim 8x8 transform: wires 0..2 gates + CNOT(0,1) + CNOT(1,2), one smem round-trip.
        __syncthreads();   // buffer free (prev layer's reads done / first use)
        #pragma unroll
        for (int m = 0; m < 16; m++) ex[(warp*16 + m)*32 + lane] = a[m];
        __syncthreads();
        {
            float2 Wr[8];
            #pragma unroll
            for (int wp = 0; wp < 8; wp++) Wr[wp] = sW[l][warp][wp];
            #pragma unroll
            for (int m = 0; m < 16; m++){
                float2 acc = make_float2(0.f, 0.f);
                #pragma unroll
                for (int wp = 0; wp < 8; wp++)
                    acc = cmadd(acc, Wr[wp], ex[(wp*16 + m)*32 + lane]);
                a[m] = acc;
            }
        }

        // CNOT chain tail (after C(0,1), C(1,2) already folded into W)
        // C(2,3): ctrl = warp bit0, tgt = lane bit4
        {
            const bool c = (warp & 1) != 0;
            #pragma unroll
            for (int m = 0; m < 16; m++){
                float2 o = shflx(a[m], 16);
                if (c) a[m] = o;
            }
        }
        // C(3,4)..C(6,7): (ctrl mask, tgt mask) = (16,8),(8,4),(4,2),(2,1) within lane bits
        #pragma unroll
        for (int j = 0; j < 4; j++){
            const int cm = 16 >> j, tm = 8 >> j;
            const bool c = (lane & cm) != 0;
            #pragma unroll
            for (int m = 0; m < 16; m++){
                float2 o = shflx(a[m], tm);
                if (c) a[m] = o;
            }
        }
        // C(7,8): ctrl = lane bit0, tgt = m bit3
        {
            const bool c = (lane & 1) != 0;
            #pragma unroll
            for (int m = 0; m < 8; m++){
                float2 t0 = a[m], t1 = a[m+8];
                a[m]   = c ? t1 : t0;
                a[m+8] = c ? t0 : t1;
            }
        }
        // C(8,9): ctrl m bit3, tgt m bit2
        #pragma unroll
        for (int m = 8; m < 12; m++){ float2 t = a[m]; a[m] = a[m+4]; a[m+4] = t; }
        // C(9,10): ctrl m bit2, tgt m bit1
        { float2 t;
          t=a[4];  a[4]=a[6];   a[6]=t;
          t=a[5];  a[5]=a[7];   a[7]=t;
          t=a[12]; a[12]=a[14]; a[14]=t;
          t=a[13]; a[13]=a[15]; a[15]=t; }
        // C(10,11): ctrl m bit1, tgt m bit0
        { float2 t;
          t=a[2];  a[2]=a[3];   a[3]=t;
          t=a[6];  a[6]=a[7];   a[7]=t;
          t=a[10]; a[10]=a[11]; a[11]=t;
          t=a[14]; a[14]=a[15]; a[15]=t; }
    }

    // ---- Readout: out[b] = sum_k |a_k|^2 * (sum_i w_i * (+1/-1 per bit)) + head_b
    float basec = 0.f;
    #pragma unroll
    for (int i = 0; i < 8; i++){
        float w = sHw[i];
        basec += ((tid >> (7 - i)) & 1) ? -w : w;
    }
    float partial = 0.f;
    #pragma unroll
    for (int m = 0; m < 16; m++){
        float c = basec;
        c += (m & 8) ? -sHw[8]  : sHw[8];
        c += (m & 4) ? -sHw[9]  : sHw[9];
        c += (m & 2) ? -sHw[10] : sHw[10];
        c += (m & 1) ? -sHw[11] : sHw[11];
        partial = fmaf(fmaf(a[m].x, a[m].x, a[m].y*a[m].y), c, partial);
    }
    #pragma unroll
    for (int off = 16; off; off >>= 1)
        partial += __shfl_down_sync(FULLMASK, partial, off);
    if (lane == 0) sRed[warp] = partial;
    __syncthreads();
    if (tid == 0){
        float s = hb[0];
        #pragma unroll
        for (int w = 0; w < 8; w++) s += sRed[w];
        out[b] = s;
    }
}

extern "C" void kernel_launch(void* const* d_in, const int* in_sizes, int n_in,
                              void* d_out, int out_size)
{
    const float* x      = (const float*)d_in[0];
    const float* params = (const float*)d_in[1];
    const float* hw     = (const float*)d_in[2];
    const float* hb     = (const float*)d_in[3];
    float* out = (float*)d_out;
    (void)in_sizes; (void)n_in;
    qsim_kernel<<<out_size, 256>>>(x, params, hw, hb, out);
}

// round 8
// speedup vs baseline: 1.7480x; 1.7480x over previous
#include <cuda_runtime.h>

typedef unsigned long long u64;
#define FULLMASK 0xffffffffu

// ---- f32x2 packed helpers (sm_103a) ------------------------------------
__device__ __forceinline__ u64 pk(float lo, float hi){
    u64 r; asm("mov.b64 %0, {%1, %2};" : "=l"(r) : "f"(lo), "f"(hi)); return r;
}
__device__ __forceinline__ void unpk(u64 v, float &lo, float &hi){
    asm("mov.b64 {%0, %1}, %2;" : "=f"(lo), "=f"(hi) : "l"(v));
}
__device__ __forceinline__ u64 f2mul(u64 a, u64 b){
    u64 d; asm("mul.rn.f32x2 %0, %1, %2;" : "=l"(d) : "l"(a), "l"(b)); return d;
}
__device__ __forceinline__ u64 f2fma(u64 a, u64 b, u64 c){
    u64 d; asm("fma.rn.f32x2 %0, %1, %2, %3;" : "=l"(d) : "l"(a), "l"(b), "l"(c)); return d;
}
__device__ __forceinline__ u64 shflx64(u64 v, int m){
    float a, b; unpk(v, a, b);
    a = __shfl_xor_sync(FULLMASK, a, m);
    b = __shfl_xor_sync(FULLMASK, b, m);
    return pk(a, b);
}
__device__ __forceinline__ float2 cmul(float2 a, float2 b){
    return make_float2(a.x*b.x - a.y*b.y, a.x*b.y + a.y*b.x);
}

// Packed 2x2 complex gate on pair ((X0,Y0),(X1,Y1)); g = 12 splats:
// [e*3+0]=(gx,gx) [e*3+1]=(-gy,-gy) [e*3+2]=(gy,gy), e in {00,01,10,11}
__device__ __forceinline__ void gap2(const u64* g, u64 &X0, u64 &Y0, u64 &X1, u64 &Y1){
    u64 nX0 = f2mul(g[0], X0); nX0 = f2fma(g[1],  Y0, nX0); nX0 = f2fma(g[3], X1, nX0); nX0 = f2fma(g[4],  Y1, nX0);
    u64 nY0 = f2mul(g[0], Y0); nY0 = f2fma(g[2],  X0, nY0); nY0 = f2fma(g[3], Y1, nY0); nY0 = f2fma(g[5],  X1, nY0);
    u64 nX1 = f2mul(g[6], X0); nX1 = f2fma(g[7],  Y0, nX1); nX1 = f2fma(g[9], X1, nX1); nX1 = f2fma(g[10], Y1, nX1);
    u64 nY1 = f2mul(g[6], Y0); nY1 = f2fma(g[8],  X0, nY1); nY1 = f2fma(g[9], Y1, nY1); nY1 = f2fma(g[11], X1, nY1);
    X0 = nX0; Y0 = nY0; X1 = nX1; Y1 = nY1;
}

// One CTA per sample.  Amplitude index k (12 bits):
//   wire0..2  -> warp bits (bit2=wire0)     k11..k9
//   wire3..7  -> lane bits (bit4=wire3)     k8..k4
//   wire8..10 -> p bits    (bit2=wire8)     k3..k1
//   wire11    -> f32x2 pack slot            k0
// State: X[p]=(Re slot0, Re slot1), Y[p]=(Im slot0, Im slot1), p=0..7.
// CNOT chain sigma (prefix-xor) is folded into the per-layer smem exchange:
// row = warp^(warp>>1); src lane/p/slot per sigma^-1 (pairwise xor).
__global__ void __launch_bounds__(256) qsim_kernel(
    const float* __restrict__ x,        // [B,12]
    const float* __restrict__ params,   // [3,12,3]
    const float* __restrict__ hw,       // [12]
    const float* __restrict__ hb,       // [1]
    float* __restrict__ out)            // [B]
{
    __shared__ ulonglong2 ex[2048];     // 32KB  interleaved (X,Y) packed pairs -> LDS.128
    __shared__ float2 sG[3][12][4];     // fused RY*RZ*RY scalar gates
    __shared__ u64 sGp[3][12][12];      // splat variants for packed gates
    __shared__ u64 sG3[3][8][8][3];     // Kron(G0,G1,G2) splats: x / -y / +y
    __shared__ float sC[12], sS[12], sHw[12], sRed[8];

    const int tid  = threadIdx.x;
    const int lane = tid & 31;
    const int warp = tid >> 5;
    const int b    = blockIdx.x;

    // ---- Stage 0: fused gates + per-sample RX angles
    if (tid < 36){
        int l = tid / 12, i = tid % 12;
        float pa = params[(l*12 + i)*3 + 0];
        float pb = params[(l*12 + i)*3 + 1];
        float pc = params[(l*12 + i)*3 + 2];
        float ca, sa, cb, sb, cc, sc;
        sincosf(0.5f*pa, &sa, &ca);
        sincosf(0.5f*pb, &sb, &cb);
        sincosf(0.5f*pc, &sc, &cc);
        float2 em = make_float2(cb, -sb);
        float2 ep = make_float2(cb,  sb);
        float ccca = cc*ca, scsa = sc*sa, ccsa = cc*sa, scca = sc*ca;
        sG[l][i][0] = make_float2( ccca*em.x - scsa*ep.x,  ccca*em.y - scsa*ep.y);
        sG[l][i][1] = make_float2(-ccsa*em.x - scca*ep.x, -ccsa*em.y - scca*ep.y);
        sG[l][i][2] = make_float2( scca*em.x + ccsa*ep.x,  scca*em.y + ccsa*ep.y);
        sG[l][i][3] = make_float2(-scsa*em.x + ccca*ep.x, -scsa*em.y + ccca*ep.y);
    } else if (tid >= 64 && tid < 76){
        int i = tid - 64;
        float s, c;
        sincosf(0.5f * x[b*12 + i], &s, &c);
        sC[i] = c; sS[i] = s;
        sHw[i] = hw[i];
    }
    __syncthreads();

    // splats for per-wire gates (36 gates x 4 entries)
    if (tid < 144){
        int l = tid / 48, r = tid % 48, i = r >> 2, e = r & 3;
        float2 g = sG[l][i][e];
        sGp[l][i][e*3+0] = pk( g.x,  g.x);
        sGp[l][i][e*3+1] = pk(-g.y, -g.y);
        sGp[l][i][e*3+2] = pk( g.y,  g.y);
    }
    // Kron(G0,G1,G2) splats: 3 layers x 8 rows x 8 cols
    if (tid < 192){
        int l = tid >> 6, r = tid & 63, row = r >> 3, col = r & 7;
        float2 t = cmul(sG[l][0][((row>>2)&1)*2 + ((col>>2)&1)],
                        sG[l][1][((row>>1)&1)*2 + ((col>>1)&1)]);
        t = cmul(t, sG[l][2][(row&1)*2 + (col&1)]);
        sG3[l][row][col][0] = pk( t.x,  t.x);
        sG3[l][row][col][1] = pk(-t.y, -t.y);
        sG3[l][row][col][2] = pk( t.y,  t.y);
    }
    __syncthreads();

    // ---- Init: product state after RX encoding (|0..0> -> column 0 of each RX)
    u64 X[8], Y[8];
    {
        float2 base = make_float2(1.f, 0.f);
        #pragma unroll
        for (int i = 0; i < 8; i++){
            int v = (tid >> (7 - i)) & 1;
            float2 f = v ? make_float2(0.f, -sS[i]) : make_float2(sC[i], 0.f);
            base = cmul(base, f);
        }
        float2 t8[2], t9[4], t10[8];
        t8[0] = make_float2(base.x*sC[8], base.y*sC[8]);
        t8[1] = cmul(base, make_float2(0.f, -sS[8]));
        #pragma unroll
        for (int u = 0; u < 2; u++){
            t9[2*u]   = make_float2(t8[u].x*sC[9], t8[u].y*sC[9]);
            t9[2*u+1] = cmul(t8[u], make_float2(0.f, -sS[9]));
        }
        #pragma unroll
        for (int u = 0; u < 4; u++){
            t10[2*u]   = make_float2(t9[u].x*sC[10], t9[u].y*sC[10]);
            t10[2*u+1] = cmul(t9[u], make_float2(0.f, -sS[10]));
        }
        float c11 = sC[11], s11 = sS[11];
        #pragma unroll
        for (int p = 0; p < 8; p++){
            // slot0 = t*c11 ; slot1 = t*(-i s11) = (s11*t.y, -s11*t.x)
            X[p] = pk(t10[p].x * c11,  t10[p].y * s11);
            Y[p] = pk(t10[p].y * c11, -t10[p].x * s11);
        }
    }

    // ---- 3 layers
    #pragma unroll 1
    for (int l = 0; l < 3; l++){
        // Local gates on p bits: wire8 (p^4), wire9 (p^2), wire10 (p^1) — packed
        {
            u64 g[12];
            #pragma unroll
            for (int j = 0; j < 12; j++) g[j] = sGp[l][8][j];
            #pragma unroll
            for (int p = 0; p < 4; p++) gap2(g, X[p], Y[p], X[p+4], Y[p+4]);
            #pragma unroll
            for (int j = 0; j < 12; j++) g[j] = sGp[l][9][j];
            gap2(g, X[0], Y[0], X[2], Y[2]); gap2(g, X[1], Y[1], X[3], Y[3]);
            gap2(g, X[4], Y[4], X[6], Y[6]); gap2(g, X[5], Y[5], X[7], Y[7]);
            #pragma unroll
            for (int j = 0; j < 12; j++) g[j] = sGp[l][10][j];
            gap2(g, X[0], Y[0], X[1], Y[1]); gap2(g, X[2], Y[2], X[3], Y[3]);
            gap2(g, X[4], Y[4], X[5], Y[5]); gap2(g, X[6], Y[6], X[7], Y[7]);
        }
        // Wire 11 (pack dim): scalar 2x2 across register halves
        {
            float2 g00 = sG[l][11][0], g01 = sG[l][11][1];
            float2 g10 = sG[l][11][2], g11 = sG[l][11][3];
            #pragma unroll
            for (int p = 0; p < 8; p++){
                float x0, x1, y0, y1;
                unpk(X[p], x0, x1); unpk(Y[p], y0, y1);
                float nx0 = fmaf(g00.x, x0, fmaf(-g00.y, y0, fmaf(g01.x, x1, -g01.y*y1)));
                float ny0 = fmaf(g00.x, y0, fmaf( g00.y, x0, fmaf(g01.x, y1,  g01.y*x1)));
                float nx1 = fmaf(g10.x, x0, fmaf(-g10.y, y0, fmaf(g11.x, x1, -g11.y*y1)));
                float ny1 = fmaf(g10.x, y0, fmaf( g10.y, x0, fmaf(g11.x, y1,  g11.y*x1)));
                X[p] = pk(nx0, nx1); Y[p] = pk(ny0, ny1);
            }
        }
        // Lane gates: wires 3..7, shuffle butterflies (packed math)
        #pragma unroll
        for (int w = 3; w < 8; w++){
            const int mask = 1 << (7 - w);
            const u64* gp = sGp[l][w];
            const bool hi = (lane & mask) != 0;
            u64 ax  = hi ? gp[9]  : gp[0];
            u64 ayn = hi ? gp[10] : gp[1];
            u64 ayp = hi ? gp[11] : gp[2];
            u64 bx  = hi ? gp[6]  : gp[3];
            u64 byn = hi ? gp[7]  : gp[4];
            u64 byp = hi ? gp[8]  : gp[5];
            #pragma unroll
            for (int p = 0; p < 8; p++){
                u64 OX = shflx64(X[p], mask);
                u64 OY = shflx64(Y[p], mask);
                u64 nX = f2mul(ax, X[p]); nX = f2fma(ayn, Y[p], nX);
                nX = f2fma(bx, OX, nX);   nX = f2fma(byn, OY, nX);
                u64 nY = f2mul(ax, Y[p]); nY = f2fma(ayp, X[p], nY);
                nY = f2fma(bx, OY, nY);   nY = f2fma(byp, OX, nY);
                X[p] = nX; Y[p] = nY;
            }
        }

        // Warp-dim 8x8 transform (wires 0-2) + FULL CNOT-chain sigma folded
        // into the gather addressing.  One smem round-trip, 128-bit accesses.
        __syncthreads();
        {
            int sb = warp*256 + lane;
            #pragma unroll
            for (int p = 0; p < 8; p++)
                ex[sb + p*32] = make_ulonglong2(X[p], Y[p]);
        }
        __syncthreads();
        {
            const int row = warp ^ (warp >> 1);
            const int uu  = ((lane & 1) << 7) |
                            ((lane ^ (lane >> 1)) ^ ((warp & 1) << 4));
            #pragma unroll
            for (int v = 0; v < 8; v++){
                u64 gx  = sG3[l][row][v][0];
                u64 gyn = sG3[l][row][v][1];
                u64 gyp = sG3[l][row][v][2];
                #pragma unroll
                for (int p = 0; p < 8; p++){
                    const int t = (((p ^ (p >> 1)) << 5) ^ uu) + v*256;
                    ulonglong2 s = ex[t];
                    if (v == 0){
                        X[p] = f2mul(gx, s.x); X[p] = f2fma(gyn, s.y, X[p]);
                        Y[p] = f2mul(gx, s.y); Y[p] = f2fma(gyp, s.x, Y[p]);
                    } else {
                        X[p] = f2fma(gx, s.x, X[p]); X[p] = f2fma(gyn, s.y, X[p]);
                        Y[p] = f2fma(gx, s.y, Y[p]); Y[p] = f2fma(gyp, s.x, Y[p]);
                    }
                }
            }
            // sigma swaps the pack slots when dest p bit0 = 1
            #pragma unroll
            for (int p = 1; p < 8; p += 2){
                float a0, a1;
                unpk(X[p], a0, a1); X[p] = pk(a1, a0);
                unpk(Y[p], a0, a1); Y[p] = pk(a1, a0);
            }
        }
    }

    // ---- Readout: out[b] = sum_k |a_k|^2 * (sum_i w_i * (+-1)) + head_b
    float basec = 0.f;
    #pragma unroll
    for (int i = 0; i < 8; i++){
        float w = sHw[i];
        basec += ((tid >> (7 - i)) & 1) ? -w : w;
    }
    float h8 = sHw[8], h9 = sHw[9], h10 = sHw[10], h11 = sHw[11];
    u64 acc = pk(0.f, 0.f);
    #pragma unroll
    for (int p = 0; p < 8; p++){
        float cp = basec + ((p & 4) ? -h8 : h8) + ((p & 2) ? -h9 : h9)
                         + ((p & 1) ? -h10 : h10);
        u64 cpair = pk(cp + h11, cp - h11);
        u64 r2 = f2mul(X[p], X[p]);
        r2 = f2fma(Y[p], Y[p], r2);
        acc = f2fma(cpair, r2, acc);
    }
    float plo, phi; unpk(acc, plo, phi);
    float partial = plo + phi;
    #pragma unroll
    for (int off = 16; off; off >>= 1)
        partial += __shfl_down_sync(FULLMASK, partial, off);
    if (lane == 0) sRed[warp] = partial;
    __syncthreads();
    if (tid == 0){
        float s = hb[0];
        #pragma unroll
        for (int w = 0; w < 8; w++) s += sRed[w];
        out[b] = s;
    }
}

extern "C" void kernel_launch(void* const* d_in, const int* in_sizes, int n_in,
                              void* d_out, int out_size)
{
    const float* x      = (const float*)d_in[0];
    const float* params = (const float*)d_in[1];
    const float* hw     = (const float*)d_in[2];
    const float* hb     = (const float*)d_in[3];
    float* out = (float*)d_out;
    (void)in_sizes; (void)n_in;
    qsim_kernel<<<out_size, 256>>>(x, params, hw, hb, out);
}

// round 9
// speedup vs baseline: 1.9364x; 1.1078x over previous
#include <cuda_runtime.h>

typedef unsigned long long u64;
#define FULLMASK 0xffffffffu

// ---- f32x2 packed helpers (sm_103a) ------------------------------------
__device__ __forceinline__ u64 pk(float lo, float hi){
    u64 r; asm("mov.b64 %0, {%1, %2};" : "=l"(r) : "f"(lo), "f"(hi)); return r;
}
__device__ __forceinline__ void unpk(u64 v, float &lo, float &hi){
    asm("mov.b64 {%0, %1}, %2;" : "=f"(lo), "=f"(hi) : "l"(v));
}
__device__ __forceinline__ u64 f2mul(u64 a, u64 b){
    u64 d; asm("mul.rn.f32x2 %0, %1, %2;" : "=l"(d) : "l"(a), "l"(b)); return d;
}
__device__ __forceinline__ u64 f2fma(u64 a, u64 b, u64 c){
    u64 d; asm("fma.rn.f32x2 %0, %1, %2, %3;" : "=l"(d) : "l"(a), "l"(b), "l"(c)); return d;
}
__device__ __forceinline__ u64 shflx64(u64 v, int m){
    float a, b; unpk(v, a, b);
    a = __shfl_xor_sync(FULLMASK, a, m);
    b = __shfl_xor_sync(FULLMASK, b, m);
    return pk(a, b);
}
__device__ __forceinline__ u64 swap_slots(u64 v){
    float a, b; unpk(v, a, b); return pk(b, a);
}
__device__ __forceinline__ float2 cmul(float2 a, float2 b){
    return make_float2(a.x*b.x - a.y*b.y, a.x*b.y + a.y*b.x);
}

// Packed 2x2 complex gate on pair ((X0,Y0),(X1,Y1)); g = 12 splats:
// [e*3+0]=(gx,gx) [e*3+1]=(-gy,-gy) [e*3+2]=(gy,gy), e in {g00,g01,g10,g11}
__device__ __forceinline__ void gap2(const u64* g, u64 &X0, u64 &Y0, u64 &X1, u64 &Y1){
    u64 nX0 = f2mul(g[0], X0); nX0 = f2fma(g[1],  Y0, nX0); nX0 = f2fma(g[3], X1, nX0); nX0 = f2fma(g[4],  Y1, nX0);
    u64 nY0 = f2mul(g[0], Y0); nY0 = f2fma(g[2],  X0, nY0); nY0 = f2fma(g[3], Y1, nY0); nY0 = f2fma(g[5],  X1, nY0);
    u64 nX1 = f2mul(g[6], X0); nX1 = f2fma(g[7],  Y0, nX1); nX1 = f2fma(g[9], X1, nX1); nX1 = f2fma(g[10], Y1, nX1);
    u64 nY1 = f2mul(g[6], Y0); nY1 = f2fma(g[8],  X0, nY1); nY1 = f2fma(g[9], Y1, nY1); nY1 = f2fma(g[11], X1, nY1);
    X0 = nX0; Y0 = nY0; X1 = nX1; Y1 = nY1;
}

// Shuffle butterfly on lane-xor 'mask'; 'hi' selects gate row (true bit / parity).
__device__ __forceinline__ void bfly(const u64* gp, int mask, bool hi, u64* X, u64* Y){
    u64 ax  = hi ? gp[9]  : gp[0];
    u64 ayn = hi ? gp[10] : gp[1];
    u64 ayp = hi ? gp[11] : gp[2];
    u64 bx  = hi ? gp[6]  : gp[3];
    u64 byn = hi ? gp[7]  : gp[4];
    u64 byp = hi ? gp[8]  : gp[5];
    #pragma unroll
    for (int p = 0; p < 8; p++){
        u64 OX = shflx64(X[p], mask);
        u64 OY = shflx64(Y[p], mask);
        u64 nX = f2mul(ax, X[p]); nX = f2fma(ayn, Y[p], nX);
        nX = f2fma(bx, OX, nX);   nX = f2fma(byn, OY, nX);
        u64 nY = f2mul(ax, Y[p]); nY = f2fma(ayp, X[p], nY);
        nY = f2fma(bx, OY, nY);   nY = f2fma(byp, OX, nY);
        X[p] = nX; Y[p] = nY;
    }
}

// Butterfly on combined mask (lane bit0 XOR p bit2): partner at (lane^1, p^4).
__device__ __forceinline__ void bfly_lp(const u64* gp, bool hi, u64* X, u64* Y){
    u64 ax  = hi ? gp[9]  : gp[0];
    u64 ayn = hi ? gp[10] : gp[1];
    u64 ayp = hi ? gp[11] : gp[2];
    u64 bx  = hi ? gp[6]  : gp[3];
    u64 byn = hi ? gp[7]  : gp[4];
    u64 byp = hi ? gp[8]  : gp[5];
    #pragma unroll
    for (int p = 0; p < 4; p++){
        u64 OXa = shflx64(X[p+4], 1), OYa = shflx64(Y[p+4], 1);
        u64 OXb = shflx64(X[p],   1), OYb = shflx64(Y[p],   1);
        u64 nX0 = f2mul(ax, X[p]);   nX0 = f2fma(ayn, Y[p],   nX0); nX0 = f2fma(bx, OXa, nX0); nX0 = f2fma(byn, OYa, nX0);
        u64 nY0 = f2mul(ax, Y[p]);   nY0 = f2fma(ayp, X[p],   nY0); nY0 = f2fma(bx, OYa, nY0); nY0 = f2fma(byp, OXa, nY0);
        u64 nX1 = f2mul(ax, X[p+4]); nX1 = f2fma(ayn, Y[p+4], nX1); nX1 = f2fma(bx, OXb, nX1); nX1 = f2fma(byn, OYb, nX1);
        u64 nY1 = f2mul(ax, Y[p+4]); nY1 = f2fma(ayp, X[p+4], nY1); nY1 = f2fma(bx, OYb, nY1); nY1 = f2fma(byp, OXb, nY1);
        X[p] = nX0; Y[p] = nY0; X[p+4] = nX1; Y[p+4] = nY1;
    }
}

// One CTA per sample.  4096 amps = 256 threads x 8 f32x2-packed complex pairs.
// Layout A: warp b2..b0 = wires 0,1,2; lane b4..b0 = wires 3..7; p b2..b0 = wires 8,9,10; slot = wire11.
// Layout B: warp b2..b0 = wires 5,6,7; lane b4..b0 = wires 0..4;  p/slot unchanged.
// The CNOT chain sigma (prefix-xor) is bit-linear: gates on warp wires are pulled
// forward through sigma as 2-bit-mask butterflies (sigma^-1(e_w)=e_w^e_{w+1}), so
// each cross-warp exchange is a PURE permutation (8 STS.128 + 8 LDS.128).
// Layer-1 warp-wire gates fold into the product-state init; sigma_3 folds into
// the readout coefficients (prefix parities) -> only 2 exchanges total.
__global__ void __launch_bounds__(256) qsim_kernel(
    const float* __restrict__ x,        // [B,12]
    const float* __restrict__ params,   // [3,12,3]
    const float* __restrict__ hw,       // [12]
    const float* __restrict__ hb,       // [1]
    float* __restrict__ out)            // [B]
{
    __shared__ ulonglong2 ex[2048];     // 32KB exchange buffer
    __shared__ float2 sG[3][12][4];     // fused RY*RZ*RY scalar gates
    __shared__ u64 sGp[3][12][12];      // splat variants for packed gates
    __shared__ float2 sU[3][2];         // layer-1 gates (wires 0-2) folded into RX init vectors
    __shared__ float sC[12], sS[12], sHw[12], sRed[8];

    const int tid  = threadIdx.x;
    const int lane = tid & 31;
    const int warp = tid >> 5;
    const int b    = blockIdx.x;

    // ---- Stage 0: fused gates + per-sample RX angles
    if (tid < 36){
        int l = tid / 12, i = tid % 12;
        float pa = params[(l*12 + i)*3 + 0];
        float pb = params[(l*12 + i)*3 + 1];
        float pc = params[(l*12 + i)*3 + 2];
        float ca, sa, cb, sb, cc, sc;
        sincosf(0.5f*pa, &sa, &ca);
        sincosf(0.5f*pb, &sb, &cb);
        sincosf(0.5f*pc, &sc, &cc);
        float2 em = make_float2(cb, -sb);
        float2 ep = make_float2(cb,  sb);
        float ccca = cc*ca, scsa = sc*sa, ccsa = cc*sa, scca = sc*ca;
        sG[l][i][0] = make_float2( ccca*em.x - scsa*ep.x,  ccca*em.y - scsa*ep.y);
        sG[l][i][1] = make_float2(-ccsa*em.x - scca*ep.x, -ccsa*em.y - scca*ep.y);
        sG[l][i][2] = make_float2( scca*em.x + ccsa*ep.x,  scca*em.y + ccsa*ep.y);
        sG[l][i][3] = make_float2(-scsa*em.x + ccca*ep.x, -scsa*em.y + ccca*ep.y);
    } else if (tid >= 64 && tid < 76){
        int i = tid - 64;
        float s, c;
        sincosf(0.5f * x[b*12 + i], &s, &c);
        sC[i] = c; sS[i] = s;
        sHw[i] = hw[i];
    }
    __syncthreads();

    // splats for per-wire gates
    if (tid < 144){
        int l = tid / 48, r = tid % 48, i = r >> 2, e = r & 3;
        float2 g = sG[l][i][e];
        sGp[l][i][e*3+0] = pk( g.x,  g.x);
        sGp[l][i][e*3+1] = pk(-g.y, -g.y);
        sGp[l][i][e*3+2] = pk( g.y,  g.y);
    } else if (tid >= 192 && tid < 195){
        // sU[w] = G1_w * (cos, -i sin)  (fold layer-1 wires 0-2 into init)
        int w = tid - 192;
        float c = sC[w], s = sS[w];
        float2 g00 = sG[0][w][0], g01 = sG[0][w][1];
        float2 g10 = sG[0][w][2], g11 = sG[0][w][3];
        sU[w][0] = make_float2(g00.x*c + g01.y*s, g00.y*c - g01.x*s);
        sU[w][1] = make_float2(g10.x*c + g11.y*s, g10.y*c - g11.x*s);
    }
    __syncthreads();

    // ---- Init: product state (RX encoding, with G1 on wires 0-2 folded in)
    u64 X[8], Y[8];
    {
        float2 base = make_float2(1.f, 0.f);
        #pragma unroll
        for (int i = 0; i < 3; i++){
            int v = (tid >> (7 - i)) & 1;
            base = cmul(base, sU[i][v]);
        }
        #pragma unroll
        for (int i = 3; i < 8; i++){
            int v = (tid >> (7 - i)) & 1;
            float2 f = v ? make_float2(0.f, -sS[i]) : make_float2(sC[i], 0.f);
            base = cmul(base, f);
        }
        float2 t9[2], t10[4], t11[8];
        t9[0] = make_float2(base.x*sC[8], base.y*sC[8]);
        t9[1] = cmul(base, make_float2(0.f, -sS[8]));
        #pragma unroll
        for (int u = 0; u < 2; u++){
            t10[2*u]   = make_float2(t9[u].x*sC[9], t9[u].y*sC[9]);
            t10[2*u+1] = cmul(t9[u], make_float2(0.f, -sS[9]));
        }
        #pragma unroll
        for (int u = 0; u < 4; u++){
            t11[2*u]   = make_float2(t10[u].x*sC[10], t10[u].y*sC[10]);
            t11[2*u+1] = cmul(t10[u], make_float2(0.f, -sS[10]));
        }
        float c11 = sC[11], s11 = sS[11];
        #pragma unroll
        for (int p = 0; p < 8; p++){
            X[p] = pk(t11[p].x * c11,  t11[p].y * s11);
            Y[p] = pk(t11[p].y * c11, -t11[p].x * s11);
        }
    }

    // Local-gate helper (wires 8,9,10 on p bits + wire 11 on slot), layer l
    auto local_gates = [&](int l){
        u64 g[12];
        #pragma unroll
        for (int j = 0; j < 12; j++) g[j] = sGp[l][8][j];
        #pragma unroll
        for (int p = 0; p < 4; p++) gap2(g, X[p], Y[p], X[p+4], Y[p+4]);
        #pragma unroll
        for (int j = 0; j < 12; j++) g[j] = sGp[l][9][j];
        gap2(g, X[0], Y[0], X[2], Y[2]); gap2(g, X[1], Y[1], X[3], Y[3]);
        gap2(g, X[4], Y[4], X[6], Y[6]); gap2(g, X[5], Y[5], X[7], Y[7]);
        #pragma unroll
        for (int j = 0; j < 12; j++) g[j] = sGp[l][10][j];
        gap2(g, X[0], Y[0], X[1], Y[1]); gap2(g, X[2], Y[2], X[3], Y[3]);
        gap2(g, X[4], Y[4], X[5], Y[5]); gap2(g, X[6], Y[6], X[7], Y[7]);
        float2 g00 = sG[l][11][0], g01 = sG[l][11][1];
        float2 g10 = sG[l][11][2], g11 = sG[l][11][3];
        #pragma unroll
        for (int p = 0; p < 8; p++){
            float x0, x1, y0, y1;
            unpk(X[p], x0, x1); unpk(Y[p], y0, y1);
            float nx0 = fmaf(g00.x, x0, fmaf(-g00.y, y0, fmaf(g01.x, x1, -g01.y*y1)));
            float ny0 = fmaf(g00.x, y0, fmaf( g00.y, x0, fmaf(g01.x, y1,  g01.y*x1)));
            float nx1 = fmaf(g10.x, x0, fmaf(-g10.y, y0, fmaf(g11.x, x1, -g11.y*y1)));
            float ny1 = fmaf(g10.x, y0, fmaf( g10.y, x0, fmaf(g11.x, y1,  g11.y*x1)));
            X[p] = pk(nx0, nx1); Y[p] = pk(ny0, ny1);
        }
    };

    // ======== Phase 1 (layout A): layer-1 gates on wires 3-11 ========
    local_gates(0);
    bfly(sGp[0][3], 16, (lane>>4)&1, X, Y);
    bfly(sGp[0][4],  8, (lane>>3)&1, X, Y);
    bfly(sGp[0][5],  4, (lane>>2)&1, X, Y);
    bfly(sGp[0][6],  2, (lane>>1)&1, X, Y);
    bfly(sGp[0][7],  1,  lane&1,     X, Y);
    // Pulled layer-2 gates on wires 5,6,7 (sigma-conjugated, masks e_w^e_{w+1})
    {
        bool P5 = __popc(tid & 0xFC) & 1;   // parity wires 0..5
        bool P6 = __popc(tid & 0xFE) & 1;   // parity wires 0..6
        bool P7 = __popc(tid & 0xFF) & 1;   // parity wires 0..7
        bfly(sGp[1][5], 6, P5, X, Y);       // wires 5^6 (lane b2^b1)
        bfly(sGp[1][6], 3, P6, X, Y);       // wires 6^7 (lane b1^b0)
        bfly_lp(sGp[1][7], P7, X, Y);       // wires 7^8 (lane b0 ^ p b2)
    }

    // ---- Exchange X1: sigma + relayout A->B (pure permutation) ----
    __syncthreads();
    {
        int s0=(warp>>2)&1, s1=(warp>>1)&1, s2=warp&1;
        int s3=(lane>>4)&1, s4=(lane>>3)&1, s5=(lane>>2)&1, s6=(lane>>1)&1, s7=lane&1;
        int mb = (s2^s6) | ((s3^s7)<<1) | (s5<<2) | (s0<<3)|(s1<<4)|(s4<<5)|(s6<<6)|(s7<<7);
        #pragma unroll
        for (int p = 0; p < 8; p++){
            int addr = mb | (((p>>2)&1)<<8) | (((p>>1)&1)<<9) | ((p&1)<<10);
            ex[addr] = make_ulonglong2(X[p], Y[p]);
        }
    }
    __syncthreads();
    {
        int d0=(lane>>4)&1, d1=(lane>>3)&1, d2=(lane>>2)&1, d3=(lane>>1)&1, d4=lane&1;
        int d5=(warp>>2)&1, d6=(warp>>1)&1, d7=warp&1;
        int s0=d0, s1=d0^d1, s2=d1^d2, s3=d2^d3, s4=d3^d4, s5=d4^d5, s6=d5^d6, s7=d6^d7;
        int gb = (s2^s6) | ((s3^s7)<<1) | (s5<<2) | (s0<<3)|(s1<<4)|(s4<<5)|(s6<<6)|(s7<<7);
        #pragma unroll
        for (int p = 0; p < 8; p++){
            int d8=(p>>2)&1, d9=(p>>1)&1, d10=p&1;
            int s8=d7^d8, s9=d8^d9, s10=d9^d10;
            ulonglong2 v = ex[gb | (s8<<8)|(s9<<9)|(s10<<10)];
            if (p & 1){ X[p] = swap_slots(v.x); Y[p] = swap_slots(v.y); }
            else      { X[p] = v.x;            Y[p] = v.y; }
        }
    }

    // ======== Phase 2 (layout B): layer-2 gates on wires 0-4, 8-11 ========
    local_gates(1);
    bfly(sGp[1][0], 16, (lane>>4)&1, X, Y);
    bfly(sGp[1][1],  8, (lane>>3)&1, X, Y);
    bfly(sGp[1][2],  4, (lane>>2)&1, X, Y);
    bfly(sGp[1][3],  2, (lane>>1)&1, X, Y);
    bfly(sGp[1][4],  1,  lane&1,     X, Y);
    // Pulled layer-3 gates on wires 0,1,2 (masks e_w^e_{w+1}, all lane bits in B)
    {
        bool P0 = (lane>>4)&1;
        bool P1 = __popc(lane & 24) & 1;
        bool P2 = __popc(lane & 28) & 1;
        bfly(sGp[2][0], 24, P0, X, Y);      // wires 0^1 (lane b4^b3)
        bfly(sGp[2][1], 12, P1, X, Y);      // wires 1^2 (lane b3^b2)
        bfly(sGp[2][2],  6, P2, X, Y);      // wires 2^3 (lane b2^b1)
    }

    // ---- Exchange X2: sigma + relayout B->A (pure permutation) ----
    __syncthreads();
    {
        // store: thread in layout B: wires 0-4 = lane b4..b0, wires 5-7 = warp b2..b0
        int s0=(lane>>4)&1, s1=(lane>>3)&1, s2=(lane>>2)&1, s3=(lane>>1)&1, s4=lane&1;
        int s5=(warp>>2)&1, s6=(warp>>1)&1, s7=warp&1;
        int mb = (s5^s3) | ((s7^s4)<<1) | (s0<<3)|(s1<<4)|(s2<<5)|(s3<<6)|(s4<<7)|(s6<<8);
        #pragma unroll
        for (int p = 0; p < 8; p++){
            int s8=(p>>2)&1, s9=(p>>1)&1, s10=p&1;
            ex[mb | ((s8^s2)<<2) | (s9<<9)|(s10<<10)] = make_ulonglong2(X[p], Y[p]);
        }
    }
    __syncthreads();
    {
        // gather: dst layout A
        int d0=(warp>>2)&1, d1=(warp>>1)&1, d2=warp&1;
        int d3=(lane>>4)&1, d4=(lane>>3)&1, d5=(lane>>2)&1, d6=(lane>>1)&1, d7=lane&1;
        int s0=d0, s1=d0^d1, s2=d1^d2, s3=d2^d3, s4=d3^d4, s5=d4^d5, s6=d5^d6, s7=d6^d7;
        int gb = (s5^s3) | ((s7^s4)<<1) | (s0<<3)|(s1<<4)|(s2<<5)|(s3<<6)|(s4<<7)|(s6<<8);
        #pragma unroll
        for (int p = 0; p < 8; p++){
            int d8=(p>>2)&1, d9=(p>>1)&1, d10=p&1;
            int s8=d7^d8, s9=d8^d9, s10=d9^d10;
            ulonglong2 v = ex[gb | ((s8^s2)<<2) | (s9<<9)|(s10<<10)];
            if (p & 1){ X[p] = swap_slots(v.x); Y[p] = swap_slots(v.y); }
            else      { X[p] = v.x;            Y[p] = v.y; }
        }
    }

    // ======== Phase 3 (layout A): layer-3 gates on wires 3-11 ========
    local_gates(2);
    bfly(sGp[2][3], 16, (lane>>4)&1, X, Y);
    bfly(sGp[2][4],  8, (lane>>3)&1, X, Y);
    bfly(sGp[2][5],  4, (lane>>2)&1, X, Y);
    bfly(sGp[2][6],  2, (lane>>1)&1, X, Y);
    bfly(sGp[2][7],  1,  lane&1,     X, Y);

    // ---- Readout: sigma_3 folded via prefix parities.
    // true bit of wire i = parity of storage wire bits 0..i
    int P = 0; float basec = 0.f;
    #pragma unroll
    for (int i = 0; i < 8; i++){
        P ^= (tid >> (7 - i)) & 1;
        basec += P ? -sHw[i] : sHw[i];
    }
    float h8 = sHw[8], h9 = sHw[9], h10 = sHw[10], h11 = sHw[11];
    u64 acc = pk(0.f, 0.f);
    #pragma unroll
    for (int p = 0; p < 8; p++){
        int P8  = P  ^ ((p>>2)&1);
        int P9  = P8 ^ ((p>>1)&1);
        int P10 = P9 ^ (p&1);
        float cp = basec + (P8 ? -h8 : h8) + (P9 ? -h9 : h9) + (P10 ? -h10 : h10);
        float t11 = P10 ? -h11 : h11;
        u64 cpair = pk(cp + t11, cp - t11);
        u64 r2 = f2mul(X[p], X[p]);
        r2 = f2fma(Y[p], Y[p], r2);
        acc = f2fma(cpair, r2, acc);
    }
    float plo, phi; unpk(acc, plo, phi);
    float partial = plo + phi;
    #pragma unroll
    for (int off = 16; off; off >>= 1)
        partial += __shfl_down_sync(FULLMASK, partial, off);
    if (lane == 0) sRed[warp] = partial;
    __syncthreads();
    if (tid == 0){
        float s = hb[0];
        #pragma unroll
        for (int w = 0; w < 8; w++) s += sRed[w];
        out[b] = s;
    }
}

extern "C" void kernel_launch(void* const* d_in, const int* in_sizes, int n_in,
                              void* d_out, int out_size)
{
    const float* x      = (const float*)d_in[0];
    const float* params = (const float*)d_in[1];
    const float* hw     = (const float*)d_in[2];
    const float* hb     = (const float*)d_in[3];
    float* out = (float*)d_out;
    (void)in_sizes; (void)n_in;
    qsim_kernel<<<out_size, 256>>>(x, params, hw, hb, out);
}

// round 10
// speedup vs baseline: 2.1948x; 1.1334x over previous
#include <cuda_runtime.h>

typedef unsigned long long u64;
#define FULLMASK 0xffffffffu

// ---- f32x2 packed helpers (sm_103a) ------------------------------------
__device__ __forceinline__ u64 pk(float lo, float hi){
    u64 r; asm("mov.b64 %0, {%1, %2};" : "=l"(r) : "f"(lo), "f"(hi)); return r;
}
__device__ __forceinline__ void unpk(u64 v, float &lo, float &hi){
    asm("mov.b64 {%0, %1}, %2;" : "=f"(lo), "=f"(hi) : "l"(v));
}
__device__ __forceinline__ u64 f2mul(u64 a, u64 b){
    u64 d; asm("mul.rn.f32x2 %0, %1, %2;" : "=l"(d) : "l"(a), "l"(b)); return d;
}
__device__ __forceinline__ u64 f2fma(u64 a, u64 b, u64 c){
    u64 d; asm("fma.rn.f32x2 %0, %1, %2, %3;" : "=l"(d) : "l"(a), "l"(b), "l"(c)); return d;
}
__device__ __forceinline__ u64 shflx64(u64 v, int m){
    float a, b; unpk(v, a, b);
    a = __shfl_xor_sync(FULLMASK, a, m);
    b = __shfl_xor_sync(FULLMASK, b, m);
    return pk(a, b);
}
__device__ __forceinline__ u64 swap_slots(u64 v){
    float a, b; unpk(v, a, b); return pk(b, a);
}
__device__ __forceinline__ float2 cmul(float2 a, float2 b){
    return make_float2(a.x*b.x - a.y*b.y, a.x*b.y + a.y*b.x);
}

// Splat table layout (row-contiguous, 12 u64 per gate):
//   row0 (lo):  [0..2] = g00 splats (x, -y, +y),  [3..5] = g01 splats
//   row1 (hi):  [6..8] = g11 splats,              [9..11] = g10 splats
// bfly coefficient fetch for a lane is then just gp + 6*hi, roles [diag|off].

// Packed 2x2 complex gate on pair ((X0,Y0),(X1,Y1)) using the new layout.
__device__ __forceinline__ void gap2(const u64* g, u64 &X0, u64 &Y0, u64 &X1, u64 &Y1){
    u64 nX0 = f2mul(g[0], X0); nX0 = f2fma(g[1],  Y0, nX0); nX0 = f2fma(g[3], X1, nX0); nX0 = f2fma(g[4],  Y1, nX0);
    u64 nY0 = f2mul(g[0], Y0); nY0 = f2fma(g[2],  X0, nY0); nY0 = f2fma(g[3], Y1, nY0); nY0 = f2fma(g[5],  X1, nY0);
    u64 nX1 = f2mul(g[9], X0); nX1 = f2fma(g[10], Y0, nX1); nX1 = f2fma(g[6], X1, nX1); nX1 = f2fma(g[7],  Y1, nX1);
    u64 nY1 = f2mul(g[9], Y0); nY1 = f2fma(g[11], X0, nY1); nY1 = f2fma(g[6], Y1, nY1); nY1 = f2fma(g[8],  X1, nY1);
    X0 = nX0; Y0 = nY0; X1 = nX1; Y1 = nY1;
}

// Shuffle butterfly on lane-xor 'mask'; 'hi' selects gate row (true bit / parity).
__device__ __forceinline__ void bfly(const u64* gp, int mask, bool hi, u64* X, u64* Y){
    const u64* gr = gp + (hi ? 6 : 0);
    u64 ax = gr[0], ayn = gr[1], ayp = gr[2];
    u64 bx = gr[3], byn = gr[4], byp = gr[5];
    #pragma unroll
    for (int p = 0; p < 8; p++){
        u64 OX = shflx64(X[p], mask);
        u64 OY = shflx64(Y[p], mask);
        u64 nX = f2mul(ax, X[p]); nX = f2fma(ayn, Y[p], nX);
        nX = f2fma(bx, OX, nX);   nX = f2fma(byn, OY, nX);
        u64 nY = f2mul(ax, Y[p]); nY = f2fma(ayp, X[p], nY);
        nY = f2fma(bx, OY, nY);   nY = f2fma(byp, OX, nY);
        X[p] = nX; Y[p] = nY;
    }
}

// Butterfly on combined mask (lane bit0 XOR p bit2): partner at (lane^1, p^4).
__device__ __forceinline__ void bfly_lp(const u64* gp, bool hi, u64* X, u64* Y){
    const u64* gr = gp + (hi ? 6 : 0);
    u64 ax = gr[0], ayn = gr[1], ayp = gr[2];
    u64 bx = gr[3], byn = gr[4], byp = gr[5];
    #pragma unroll
    for (int p = 0; p < 4; p++){
        u64 OXa = shflx64(X[p+4], 1), OYa = shflx64(Y[p+4], 1);
        u64 OXb = shflx64(X[p],   1), OYb = shflx64(Y[p],   1);
        u64 nX0 = f2mul(ax, X[p]);   nX0 = f2fma(ayn, Y[p],   nX0); nX0 = f2fma(bx, OXa, nX0); nX0 = f2fma(byn, OYa, nX0);
        u64 nY0 = f2mul(ax, Y[p]);   nY0 = f2fma(ayp, X[p],   nY0); nY0 = f2fma(bx, OYa, nY0); nY0 = f2fma(byp, OXa, nY0);
        u64 nX1 = f2mul(ax, X[p+4]); nX1 = f2fma(ayn, Y[p+4], nX1); nX1 = f2fma(bx, OXb, nX1); nX1 = f2fma(byn, OYb, nX1);
        u64 nY1 = f2mul(ax, Y[p+4]); nY1 = f2fma(ayp, X[p+4], nY1); nY1 = f2fma(bx, OYb, nY1); nY1 = f2fma(byp, OXb, nY1);
        X[p] = nX0; Y[p] = nY0; X[p+4] = nX1; Y[p+4] = nY1;
    }
}

// One CTA per sample.  4096 amps = 256 threads x 8 f32x2-packed complex pairs.
// Layout A: warp b2..b0 = wires 0,1,2; lane b4..b0 = wires 3..7; p b2..b0 = wires 8,9,10; slot = wire11.
// Layout B: warp b2..b0 = wires 5,6,7; lane b4..b0 = wires 0..4;  p/slot unchanged.
// CNOT chain sigma (prefix-xor) is bit-linear: warp-wire gates are pulled forward
// through sigma as 2-bit-mask butterflies; each cross-warp exchange is a PURE
// permutation (8 STS.128 + 8 LDS.128).  Layer-1 warp-wire gates fold into the
// product-state init; sigma_3 folds into the readout -> 2 exchanges total.
__global__ void __launch_bounds__(256, 3) qsim_kernel(
    const float* __restrict__ x,        // [B,12]
    const float* __restrict__ params,   // [3,12,3]
    const float* __restrict__ hw,       // [12]
    const float* __restrict__ hb,       // [1]
    float* __restrict__ out)            // [B]
{
    __shared__ ulonglong2 ex[2048];     // 32KB exchange buffer
    __shared__ float2 sG[3][12][4];     // fused RY*RZ*RY scalar gates
    __shared__ u64 sGp[3][12][12];      // splat variants (row-contiguous layout)
    __shared__ float2 sU[3][2];         // layer-1 gates (wires 0-2) folded into RX init vectors
    __shared__ float sC[12], sS[12], sHw[12], sRed[8];

    const int tid  = threadIdx.x;
    const int lane = tid & 31;
    const int warp = tid >> 5;
    const int b    = blockIdx.x;

    // ---- Stage 0: fused gates + per-sample RX angles
    if (tid < 36){
        int l = tid / 12, i = tid % 12;
        float pa = params[(l*12 + i)*3 + 0];
        float pb = params[(l*12 + i)*3 + 1];
        float pc = params[(l*12 + i)*3 + 2];
        float ca, sa, cb, sb, cc, sc;
        sincosf(0.5f*pa, &sa, &ca);
        sincosf(0.5f*pb, &sb, &cb);
        sincosf(0.5f*pc, &sc, &cc);
        float2 em = make_float2(cb, -sb);
        float2 ep = make_float2(cb,  sb);
        float ccca = cc*ca, scsa = sc*sa, ccsa = cc*sa, scca = sc*ca;
        sG[l][i][0] = make_float2( ccca*em.x - scsa*ep.x,  ccca*em.y - scsa*ep.y);
        sG[l][i][1] = make_float2(-ccsa*em.x - scca*ep.x, -ccsa*em.y - scca*ep.y);
        sG[l][i][2] = make_float2( scca*em.x + ccsa*ep.x,  scca*em.y + ccsa*ep.y);
        sG[l][i][3] = make_float2(-scsa*em.x + ccca*ep.x, -scsa*em.y + ccca*ep.y);
    } else if (tid >= 64 && tid < 76){
        int i = tid - 64;
        float s, c;
        sincosf(0.5f * x[b*12 + i], &s, &c);
        sC[i] = c; sS[i] = s;
        sHw[i] = hw[i];
    }
    __syncthreads();

    // splats for per-wire gates (row-contiguous: e=0(g00)->0, 1(g01)->3, 3(g11)->6, 2(g10)->9)
    if (tid < 144){
        int l = tid / 48, r = tid % 48, i = r >> 2, e = r & 3;
        float2 g = sG[l][i][e];
        int base = 3 * (e ^ (e >> 1));
        sGp[l][i][base+0] = pk( g.x,  g.x);
        sGp[l][i][base+1] = pk(-g.y, -g.y);
        sGp[l][i][base+2] = pk( g.y,  g.y);
    } else if (tid >= 192 && tid < 195){
        // sU[w] = G1_w * (cos, -i sin)  (fold layer-1 wires 0-2 into init)
        int w = tid - 192;
        float c = sC[w], s = sS[w];
        float2 g00 = sG[0][w][0], g01 = sG[0][w][1];
        float2 g10 = sG[0][w][2], g11 = sG[0][w][3];
        sU[w][0] = make_float2(g00.x*c + g01.y*s, g00.y*c - g01.x*s);
        sU[w][1] = make_float2(g10.x*c + g11.y*s, g10.y*c - g11.x*s);
    }
    __syncthreads();

    // ---- Init: product state (RX encoding, with G1 on wires 0-2 folded in)
    u64 X[8], Y[8];
    {
        float2 base = make_float2(1.f, 0.f);
        #pragma unroll
        for (int i = 0; i < 3; i++){
            int v = (tid >> (7 - i)) & 1;
            base = cmul(base, sU[i][v]);
        }
        #pragma unroll
        for (int i = 3; i < 8; i++){
            int v = (tid >> (7 - i)) & 1;
            float2 f = v ? make_float2(0.f, -sS[i]) : make_float2(sC[i], 0.f);
            base = cmul(base, f);
        }
        float2 t9[2], t10[4], t11[8];
        t9[0] = make_float2(base.x*sC[8], base.y*sC[8]);
        t9[1] = cmul(base, make_float2(0.f, -sS[8]));
        #pragma unroll
        for (int u = 0; u < 2; u++){
            t10[2*u]   = make_float2(t9[u].x*sC[9], t9[u].y*sC[9]);
            t10[2*u+1] = cmul(t9[u], make_float2(0.f, -sS[9]));
        }
        #pragma unroll
        for (int u = 0; u < 4; u++){
            t11[2*u]   = make_float2(t10[u].x*sC[10], t10[u].y*sC[10]);
            t11[2*u+1] = cmul(t10[u], make_float2(0.f, -sS[10]));
        }
        float c11 = sC[11], s11 = sS[11];
        #pragma unroll
        for (int p = 0; p < 8; p++){
            X[p] = pk(t11[p].x * c11,  t11[p].y * s11);
            Y[p] = pk(t11[p].y * c11, -t11[p].x * s11);
        }
    }

    // Local-gate helper (wires 8,9,10 on p bits + wire 11 on slot), layer l
    auto local_gates = [&](int l){
        {
            const u64* g = sGp[l][8];
            #pragma unroll
            for (int p = 0; p < 4; p++) gap2(g, X[p], Y[p], X[p+4], Y[p+4]);
        }
        {
            const u64* g = sGp[l][9];
            gap2(g, X[0], Y[0], X[2], Y[2]); gap2(g, X[1], Y[1], X[3], Y[3]);
            gap2(g, X[4], Y[4], X[6], Y[6]); gap2(g, X[5], Y[5], X[7], Y[7]);
        }
        {
            const u64* g = sGp[l][10];
            gap2(g, X[0], Y[0], X[1], Y[1]); gap2(g, X[2], Y[2], X[3], Y[3]);
            gap2(g, X[4], Y[4], X[5], Y[5]); gap2(g, X[6], Y[6], X[7], Y[7]);
        }
        float2 g00 = sG[l][11][0], g01 = sG[l][11][1];
        float2 g10 = sG[l][11][2], g11 = sG[l][11][3];
        #pragma unroll
        for (int p = 0; p < 8; p++){
            float x0, x1, y0, y1;
            unpk(X[p], x0, x1); unpk(Y[p], y0, y1);
            float nx0 = fmaf(g00.x, x0, fmaf(-g00.y, y0, fmaf(g01.x, x1, -g01.y*y1)));
            float ny0 = fmaf(g00.x, y0, fmaf( g00.y, x0, fmaf(g01.x, y1,  g01.y*x1)));
            float nx1 = fmaf(g10.x, x0, fmaf(-g10.y, y0, fmaf(g11.x, x1, -g11.y*y1)));
            float ny1 = fmaf(g10.x, y0, fmaf( g10.y, x0, fmaf(g11.x, y1,  g11.y*x1)));
            X[p] = pk(nx0, nx1); Y[p] = pk(ny0, ny1);
        }
    };

    // ======== Phase 1 (layout A): layer-1 gates on wires 3-11 ========
    local_gates(0);
    bfly(sGp[0][3], 16, (lane>>4)&1, X, Y);
    bfly(sGp[0][4],  8, (lane>>3)&1, X, Y);
    bfly(sGp[0][5],  4, (lane>>2)&1, X, Y);
    bfly(sGp[0][6],  2, (lane>>1)&1, X, Y);
    bfly(sGp[0][7],  1,  lane&1,     X, Y);
    // Pulled layer-2 gates on wires 5,6,7 (sigma-conjugated, masks e_w^e_{w+1})
    {
        bool P5 = __popc(tid & 0xFC) & 1;   // parity wires 0..5
        bool P6 = __popc(tid & 0xFE) & 1;   // parity wires 0..6
        bool P7 = __popc(tid & 0xFF) & 1;   // parity wires 0..7
        bfly(sGp[1][5], 6, P5, X, Y);       // wires 5^6 (lane b2^b1)
        bfly(sGp[1][6], 3, P6, X, Y);       // wires 6^7 (lane b1^b0)
        bfly_lp(sGp[1][7], P7, X, Y);       // wires 7^8 (lane b0 ^ p b2)
    }

    // ---- Exchange X1: sigma + relayout A->B (pure permutation) ----
    __syncthreads();
    {
        int s0=(warp>>2)&1, s1=(warp>>1)&1, s2=warp&1;
        int s3=(lane>>4)&1, s4=(lane>>3)&1, s5=(lane>>2)&1, s6=(lane>>1)&1, s7=lane&1;
        int mb = (s2^s6) | ((s3^s7)<<1) | (s5<<2) | (s0<<3)|(s1<<4)|(s4<<5)|(s6<<6)|(s7<<7);
        #pragma unroll
        for (int p = 0; p < 8; p++){
            int addr = mb | (((p>>2)&1)<<8) | (((p>>1)&1)<<9) | ((p&1)<<10);
            ex[addr] = make_ulonglong2(X[p], Y[p]);
        }
    }
    __syncthreads();
    {
        int d0=(lane>>4)&1, d1=(lane>>3)&1, d2=(lane>>2)&1, d3=(lane>>1)&1, d4=lane&1;
        int d5=(warp>>2)&1, d6=(warp>>1)&1, d7=warp&1;
        int s0=d0, s1=d0^d1, s2=d1^d2, s3=d2^d3, s4=d3^d4, s5=d4^d5, s6=d5^d6, s7=d6^d7;
        int gb = (s2^s6) | ((s3^s7)<<1) | (s5<<2) | (s0<<3)|(s1<<4)|(s4<<5)|(s6<<6)|(s7<<7);
        #pragma unroll
        for (int p = 0; p < 8; p++){
            int d8=(p>>2)&1, d9=(p>>1)&1, d10=p&1;
            int s8=d7^d8, s9=d8^d9, s10=d9^d10;
            ulonglong2 v = ex[gb | (s8<<8)|(s9<<9)|(s10<<10)];
            if (p & 1){ X[p] = swap_slots(v.x); Y[p] = swap_slots(v.y); }
            else      { X[p] = v.x;            Y[p] = v.y; }
        }
    }

    // ======== Phase 2 (layout B): layer-2 gates on wires 0-4, 8-11 ========
    local_gates(1);
    bfly(sGp[1][0], 16, (lane>>4)&1, X, Y);
    bfly(sGp[1][1],  8, (lane>>3)&1, X, Y);
    bfly(sGp[1][2],  4, (lane>>2)&1, X, Y);
    bfly(sGp[1][3],  2, (lane>>1)&1, X, Y);
    bfly(sGp[1][4],  1,  lane&1,     X, Y);
    // Pulled layer-3 gates on wires 0,1,2 (masks e_w^e_{w+1}, all lane bits in B)
    {
        bool P0 = (lane>>4)&1;
        bool P1 = __popc(lane & 24) & 1;
        bool P2 = __popc(lane & 28) & 1;
        bfly(sGp[2][0], 24, P0, X, Y);      // wires 0^1 (lane b4^b3)
        bfly(sGp[2][1], 12, P1, X, Y);      // wires 1^2 (lane b3^b2)
        bfly(sGp[2][2],  6, P2, X, Y);      // wires 2^3 (lane b2^b1)
    }

    // ---- Exchange X2: sigma + relayout B->A (pure permutation) ----
    __syncthreads();
    {
        int s0=(lane>>4)&1, s1=(lane>>3)&1, s2=(lane>>2)&1, s3=(lane>>1)&1, s4=lane&1;
        int s5=(warp>>2)&1, s6=(warp>>1)&1, s7=warp&1;
        int mb = (s5^s3) | ((s7^s4)<<1) | (s0<<3)|(s1<<4)|(s2<<5)|(s3<<6)|(s4<<7)|(s6<<8);
        #pragma unroll
        for (int p = 0; p < 8; p++){
            int s8=(p>>2)&1, s9=(p>>1)&1, s10=p&1;
            ex[mb | ((s8^s2)<<2) | (s9<<9)|(s10<<10)] = make_ulonglong2(X[p], Y[p]);
        }
    }
    __syncthreads();
    {
        int d0=(warp>>2)&1, d1=(warp>>1)&1, d2=warp&1;
        int d3=(lane>>4)&1, d4=(lane>>3)&1, d5=(lane>>2)&1, d6=(lane>>1)&1, d7=lane&1;
        int s0=d0, s1=d0^d1, s2=d1^d2, s3=d2^d3, s4=d3^d4, s5=d4^d5, s6=d5^d6, s7=d6^d7;
        int gb = (s5^s3) | ((s7^s4)<<1) | (s0<<3)|(s1<<4)|(s2<<5)|(s3<<6)|(s4<<7)|(s6<<8);
        #pragma unroll
        for (int p = 0; p < 8; p++){
            int d8=(p>>2)&1, d9=(p>>1)&1, d10=p&1;
            int s8=d7^d8, s9=d8^d9, s10=d9^d10;
            ulonglong2 v = ex[gb | ((s8^s2)<<2) | (s9<<9)|(s10<<10)];
            if (p & 1){ X[p] = swap_slots(v.x); Y[p] = swap_slots(v.y); }
            else      { X[p] = v.x;            Y[p] = v.y; }
        }
    }

    // ======== Phase 3 (layout A): layer-3 gates on wires 3-11 ========
    local_gates(2);
    bfly(sGp[2][3], 16, (lane>>4)&1, X, Y);
    bfly(sGp[2][4],  8, (lane>>3)&1, X, Y);
    bfly(sGp[2][5],  4, (lane>>2)&1, X, Y);
    bfly(sGp[2][6],  2, (lane>>1)&1, X, Y);
    bfly(sGp[2][7],  1,  lane&1,     X, Y);

    // ---- Readout: sigma_3 folded via prefix parities.
    int P = 0; float basec = 0.f;
    #pragma unroll
    for (int i = 0; i < 8; i++){
        P ^= (tid >> (7 - i)) & 1;
        basec += P ? -sHw[i] : sHw[i];
    }
    float h8 = sHw[8], h9 = sHw[9], h10 = sHw[10], h11 = sHw[11];
    u64 acc = pk(0.f, 0.f);
    #pragma unroll
    for (int p = 0; p < 8; p++){
        int P8  = P  ^ ((p>>2)&1);
        int P9  = P8 ^ ((p>>1)&1);
        int P10 = P9 ^ (p&1);
        float cp = basec + (P8 ? -h8 : h8) + (P9 ? -h9 : h9) + (P10 ? -h10 : h10);
        float t11 = P10 ? -h11 : h11;
        u64 cpair = pk(cp + t11, cp - t11);
        u64 r2 = f2mul(X[p], X[p]);
        r2 = f2fma(Y[p], Y[p], r2);
        acc = f2fma(cpair, r2, acc);
    }
    float plo, phi; unpk(acc, plo, phi);
    float partial = plo + phi;
    #pragma unroll
    for (int off = 16; off; off >>= 1)
        partial += __shfl_down_sync(FULLMASK, partial, off);
    if (lane == 0) sRed[warp] = partial;
    __syncthreads();
    if (tid == 0){
        float s = hb[0];
        #pragma unroll
        for (int w = 0; w < 8; w++) s += sRed[w];
        out[b] = s;
    }
}

extern "C" void kernel_launch(void* const* d_in, const int* in_sizes, int n_in,
                              void* d_out, int out_size)
{
    const float* x      = (const float*)d_in[0];
    const float* params = (const float*)d_in[1];
    const float* hw     = (const float*)d_in[2];
    const float* hb     = (const float*)d_in[3];
    float* out = (float*)d_out;
    (void)in_sizes; (void)n_in;
    qsim_kernel<<<out_size, 256>>>(x, params, hw, hb, out);
}

// round 13
// speedup vs baseline: 2.8129x; 1.2816x over previous
#include <cuda_runtime.h>

typedef unsigned long long u64;
#define FULLMASK 0xffffffffu

// ---- f32x2 packed helpers (sm_103a) ------------------------------------
__device__ __forceinline__ u64 pk(float lo, float hi){
    u64 r; asm("mov.b64 %0, {%1, %2};" : "=l"(r) : "f"(lo), "f"(hi)); return r;
}
__device__ __forceinline__ void unpk(u64 v, float &lo, float &hi){
    asm("mov.b64 {%0, %1}, %2;" : "=f"(lo), "=f"(hi) : "l"(v));
}
__device__ __forceinline__ u64 f2mul(u64 a, u64 b){
    u64 d; asm("mul.rn.f32x2 %0, %1, %2;" : "=l"(d) : "l"(a), "l"(b)); return d;
}
__device__ __forceinline__ u64 f2fma(u64 a, u64 b, u64 c){
    u64 d; asm("fma.rn.f32x2 %0, %1, %2, %3;" : "=l"(d) : "l"(a), "l"(b), "l"(c)); return d;
}
__device__ __forceinline__ u64 shflx64(u64 v, int m){
    float a, b; unpk(v, a, b);
    a = __shfl_xor_sync(FULLMASK, a, m);
    b = __shfl_xor_sync(FULLMASK, b, m);
    return pk(a, b);
}
__device__ __forceinline__ u64 swap_slots(u64 v){
    float a, b; unpk(v, a, b); return pk(b, a);
}
__device__ __forceinline__ float2 cmul(float2 a, float2 b){
    return make_float2(a.x*b.x - a.y*b.y, a.x*b.y + a.y*b.x);
}

// Splat table layout (row-contiguous, 12 u64 per gate):
//   row0 (lo):  [0..2] = g00 splats (x, -y, +y),  [3..5] = g01 splats
//   row1 (hi):  [6..8] = g11 splats,              [9..11] = g10 splats
// bfly coefficient fetch for a lane is just gp + 6*hi, roles [diag|off].

// Packed 2x2 complex gate on pair ((X0,Y0),(X1,Y1)) using the row-contiguous layout.
__device__ __forceinline__ void gap2(const u64* g, u64 &X0, u64 &Y0, u64 &X1, u64 &Y1){
    u64 nX0 = f2mul(g[0], X0); nX0 = f2fma(g[1],  Y0, nX0); nX0 = f2fma(g[3], X1, nX0); nX0 = f2fma(g[4],  Y1, nX0);
    u64 nY0 = f2mul(g[0], Y0); nY0 = f2fma(g[2],  X0, nY0); nY0 = f2fma(g[3], Y1, nY0); nY0 = f2fma(g[5],  X1, nY0);
    u64 nX1 = f2mul(g[9], X0); nX1 = f2fma(g[10], Y0, nX1); nX1 = f2fma(g[6], X1, nX1); nX1 = f2fma(g[7],  Y1, nX1);
    u64 nY1 = f2mul(g[9], Y0); nY1 = f2fma(g[11], X0, nY1); nY1 = f2fma(g[6], Y1, nY1); nY1 = f2fma(g[8],  X1, nY1);
    X0 = nX0; Y0 = nY0; X1 = nX1; Y1 = nY1;
}

// Shuffle butterfly on lane-xor 'mask'; 'hi' selects gate row (true bit / parity).
__device__ __forceinline__ void bfly(const u64* gp, int mask, bool hi, u64* X, u64* Y){
    const u64* gr = gp + (hi ? 6 : 0);
    u64 ax = gr[0], ayn = gr[1], ayp = gr[2];
    u64 bx = gr[3], byn = gr[4], byp = gr[5];
    #pragma unroll
    for (int p = 0; p < 8; p++){
        u64 OX = shflx64(X[p], mask);
        u64 OY = shflx64(Y[p], mask);
        u64 nX = f2mul(ax, X[p]); nX = f2fma(ayn, Y[p], nX);
        nX = f2fma(bx, OX, nX);   nX = f2fma(byn, OY, nX);
        u64 nY = f2mul(ax, Y[p]); nY = f2fma(ayp, X[p], nY);
        nY = f2fma(bx, OY, nY);   nY = f2fma(byp, OX, nY);
        X[p] = nX; Y[p] = nY;
    }
}

// Butterfly on combined mask (lane bit0 XOR p bit2): partner at (lane^1, p^4).
__device__ __forceinline__ void bfly_lp(const u64* gp, bool hi, u64* X, u64* Y){
    const u64* gr = gp + (hi ? 6 : 0);
    u64 ax = gr[0], ayn = gr[1], ayp = gr[2];
    u64 bx = gr[3], byn = gr[4], byp = gr[5];
    #pragma unroll
    for (int p = 0; p < 4; p++){
        u64 OXa = shflx64(X[p+4], 1), OYa = shflx64(Y[p+4], 1);
        u64 OXb = shflx64(X[p],   1), OYb = shflx64(Y[p],   1);
        u64 nX0 = f2mul(ax, X[p]);   nX0 = f2fma(ayn, Y[p],   nX0); nX0 = f2fma(bx, OXa, nX0); nX0 = f2fma(byn, OYa, nX0);
        u64 nY0 = f2mul(ax, Y[p]);   nY0 = f2fma(ayp, X[p],   nY0); nY0 = f2fma(bx, OYa, nY0); nY0 = f2fma(byp, OXa, nY0);
        u64 nX1 = f2mul(ax, X[p+4]); nX1 = f2fma(ayn, Y[p+4], nX1); nX1 = f2fma(bx, OXb, nX1); nX1 = f2fma(byn, OYb, nX1);
        u64 nY1 = f2mul(ax, Y[p+4]); nY1 = f2fma(ayp, X[p+4], nY1); nY1 = f2fma(bx, OYb, nY1); nY1 = f2fma(byp, OXb, nY1);
        X[p] = nX0; Y[p] = nY0; X[p+4] = nX1; Y[p+4] = nY1;
    }
}

// One CTA per sample.  4096 amps = 256 threads x 8 f32x2-packed complex pairs.
// Layout A: warp b2..b0 = wires 0,1,2; lane b4..b0 = wires 3..7; p b2..b0 = wires 8,9,10; slot = wire11.
// Layout B: warp b2..b0 = wires 5,6,7; lane b4..b0 = wires 0..4;  p/slot unchanged.
// CNOT chain sigma (prefix-xor) is bit-linear: warp-wire gates are pulled forward
// through sigma as 2-bit-mask butterflies; each cross-warp exchange is a PURE
// permutation (8 STS.128 + 8 LDS.128).
// The initial state (post RX encoding) is a PRODUCT state, so the ENTIRE layer 1
// (all 12 single-qubit gates) folds into per-wire init vectors v_w = G1_w(c,-is).
// sigma_3 folds into the readout coefficients -> only 2 exchanges total.
__global__ void __launch_bounds__(256, 3) qsim_kernel(
    const float* __restrict__ x,        // [B,12]
    const float* __restrict__ params,   // [3,12,3]
    const float* __restrict__ hw,       // [12]
    const float* __restrict__ hb,       // [1]
    float* __restrict__ out)            // [B]
{
    __shared__ ulonglong2 ex[2048];     // 32KB exchange buffer
    __shared__ float2 sG[3][12][4];     // fused RY*RZ*RY scalar gates
    __shared__ u64 sGp[3][12][12];      // splat variants (row-contiguous layout)
    __shared__ float2 sV[12][2];        // layer-1-folded init vectors per wire
    __shared__ float sC[12], sS[12], sHw[12], sRed[8];

    const int tid  = threadIdx.x;
    const int lane = tid & 31;
    const int warp = tid >> 5;
    const int b    = blockIdx.x;

    // ---- Stage 0: fused gates + per-sample RX angles
    if (tid < 36){
        int l = tid / 12, i = tid % 12;
        float pa = params[(l*12 + i)*3 + 0];
        float pb = params[(l*12 + i)*3 + 1];
        float pc = params[(l*12 + i)*3 + 2];
        float ca, sa, cb, sb, cc, sc;
        sincosf(0.5f*pa, &sa, &ca);
        sincosf(0.5f*pb, &sb, &cb);
        sincosf(0.5f*pc, &sc, &cc);
        float2 em = make_float2(cb, -sb);
        float2 ep = make_float2(cb,  sb);
        float ccca = cc*ca, scsa = sc*sa, ccsa = cc*sa, scca = sc*ca;
        sG[l][i][0] = make_float2( ccca*em.x - scsa*ep.x,  ccca*em.y - scsa*ep.y);
        sG[l][i][1] = make_float2(-ccsa*em.x - scca*ep.x, -ccsa*em.y - scca*ep.y);
        sG[l][i][2] = make_float2( scca*em.x + ccsa*ep.x,  scca*em.y + ccsa*ep.y);
        sG[l][i][3] = make_float2(-scsa*em.x + ccca*ep.x, -scsa*em.y + ccca*ep.y);
    } else if (tid >= 64 && tid < 76){
        int i = tid - 64;
        float s, c;
        sincosf(0.5f * x[b*12 + i], &s, &c);
        sC[i] = c; sS[i] = s;
        sHw[i] = hw[i];
    }
    __syncthreads();

    // splats for per-wire gates (row-contiguous: e=0(g00)->0, 1(g01)->3, 3(g11)->6, 2(g10)->9)
    if (tid < 144){
        int l = tid / 48, r = tid % 48, i = r >> 2, e = r & 3;
        float2 g = sG[l][i][e];
        int base = 3 * (e ^ (e >> 1));
        sGp[l][i][base+0] = pk( g.x,  g.x);
        sGp[l][i][base+1] = pk(-g.y, -g.y);
        sGp[l][i][base+2] = pk( g.y,  g.y);
    } else if (tid >= 192 && tid < 204){
        // sV[w] = G1_w * (cos, -i sin): ENTIRE layer 1 folded into product init
        int w = tid - 192;
        float c = sC[w], s = sS[w];
        float2 g00 = sG[0][w][0], g01 = sG[0][w][1];
        float2 g10 = sG[0][w][2], g11 = sG[0][w][3];
        sV[w][0] = make_float2(g00.x*c + g01.y*s, g00.y*c - g01.x*s);
        sV[w][1] = make_float2(g10.x*c + g11.y*s, g10.y*c - g11.x*s);
    }
    __syncthreads();

    // ---- Init: product state = (RX encoding) followed by all layer-1 gates
    u64 X[8], Y[8];
    {
        float2 base = sV[0][(tid >> 7) & 1];
        #pragma unroll
        for (int i = 1; i < 8; i++)
            base = cmul(base, sV[i][(tid >> (7 - i)) & 1]);
        float2 t9[2], t10[4], t11[8];
        t9[0] = cmul(base, sV[8][0]);
        t9[1] = cmul(base, sV[8][1]);
        #pragma unroll
        for (int u = 0; u < 2; u++){
            t10[2*u]   = cmul(t9[u], sV[9][0]);
            t10[2*u+1] = cmul(t9[u], sV[9][1]);
        }
        #pragma unroll
        for (int u = 0; u < 4; u++){
            t11[2*u]   = cmul(t10[u], sV[10][0]);
            t11[2*u+1] = cmul(t10[u], sV[10][1]);
        }
        float2 v0 = sV[11][0], v1 = sV[11][1];
        #pragma unroll
        for (int p = 0; p < 8; p++){
            float2 a0 = cmul(t11[p], v0);
            float2 a1 = cmul(t11[p], v1);
            X[p] = pk(a0.x, a1.x);
            Y[p] = pk(a0.y, a1.y);
        }
    }

    // Local-gate helper (wires 8,9,10 on p bits + wire 11 on slot), layer l
    auto local_gates = [&](int l){
        {
            const u64* g = sGp[l][8];
            #pragma unroll
            for (int p = 0; p < 4; p++) gap2(g, X[p], Y[p], X[p+4], Y[p+4]);
        }
        {
            const u64* g = sGp[l][9];
            gap2(g, X[0], Y[0], X[2], Y[2]); gap2(g, X[1], Y[1], X[3], Y[3]);
            gap2(g, X[4], Y[4], X[6], Y[6]); gap2(g, X[5], Y[5], X[7], Y[7]);
        }
        {
            const u64* g = sGp[l][10];
            gap2(g, X[0], Y[0], X[1], Y[1]); gap2(g, X[2], Y[2], X[3], Y[3]);
            gap2(g, X[4], Y[4], X[5], Y[5]); gap2(g, X[6], Y[6], X[7], Y[7]);
        }
        float2 g00 = sG[l][11][0], g01 = sG[l][11][1];
        float2 g10 = sG[l][11][2], g11 = sG[l][11][3];
        #pragma unroll
        for (int p = 0; p < 8; p++){
            float x0, x1, y0, y1;
            unpk(X[p], x0, x1); unpk(Y[p], y0, y1);
            float nx0 = fmaf(g00.x, x0, fmaf(-g00.y, y0, fmaf(g01.x, x1, -g01.y*y1)));
            float ny0 = fmaf(g00.x, y0, fmaf( g00.y, x0, fmaf(g01.x, y1,  g01.y*x1)));
            float nx1 = fmaf(g10.x, x0, fmaf(-g10.y, y0, fmaf(g11.x, x1, -g11.y*y1)));
            float ny1 = fmaf(g10.x, y0, fmaf( g10.y, x0, fmaf(g11.x, y1,  g11.y*x1)));
            X[p] = pk(nx0, nx1); Y[p] = pk(ny0, ny1);
        }
    };

    // ======== Phase 1 (layout A): only pulled layer-2 gates on wires 5,6,7 ========
    // (layer-1 gates all folded into init; sigma-conjugated masks e_w^e_{w+1})
    {
        bool P5 = __popc(tid & 0xFC) & 1;   // parity wires 0..5
        bool P6 = __popc(tid & 0xFE) & 1;   // parity wires 0..6
        bool P7 = __popc(tid & 0xFF) & 1;   // parity wires 0..7
        bfly(sGp[1][5], 6, P5, X, Y);       // wires 5^6 (lane b2^b1)
        bfly(sGp[1][6], 3, P6, X, Y);       // wires 6^7 (lane b1^b0)
        bfly_lp(sGp[1][7], P7, X, Y);       // wires 7^8 (lane b0 ^ p b2)
    }

    // ---- Exchange X1: sigma + relayout A->B (pure permutation) ----
    __syncthreads();
    {
        int s0=(warp>>2)&1, s1=(warp>>1)&1, s2=warp&1;
        int s3=(lane>>4)&1, s4=(lane>>3)&1, s5=(lane>>2)&1, s6=(lane>>1)&1, s7=lane&1;
        int mb = (s2^s6) | ((s3^s7)<<1) | (s5<<2) | (s0<<3)|(s1<<4)|(s4<<5)|(s6<<6)|(s7<<7);
        #pragma unroll
        for (int p = 0; p < 8; p++){
            int addr = mb | (((p>>2)&1)<<8) | (((p>>1)&1)<<9) | ((p&1)<<10);
            ex[addr] = make_ulonglong2(X[p], Y[p]);
        }
    }
    __syncthreads();
    {
        int d0=(lane>>4)&1, d1=(lane>>3)&1, d2=(lane>>2)&1, d3=(lane>>1)&1, d4=lane&1;
        int d5=(warp>>2)&1, d6=(warp>>1)&1, d7=warp&1;
        int s0=d0, s1=d0^d1, s2=d1^d2, s3=d2^d3, s4=d3^d4, s5=d4^d5, s6=d5^d6, s7=d6^d7;
        int gb = (s2^s6) | ((s3^s7)<<1) | (s5<<2) | (s0<<3)|(s1<<4)|(s4<<5)|(s6<<6)|(s7<<7);
        #pragma unroll
        for (int p = 0; p < 8; p++){
            int d8=(p>>2)&1, d9=(p>>1)&1, d10=p&1;
            int s8=d7^d8, s9=d8^d9, s10=d9^d10;
            ulonglong2 v = ex[gb | (s8<<8)|(s9<<9)|(s10<<10)];
            if (p & 1){ X[p] = swap_slots(v.x); Y[p] = swap_slots(v.y); }
            else      { X[p] = v.x;            Y[p] = v.y; }
        }
    }

    // ======== Phase 2 (layout B): layer-2 gates on wires 0-4, 8-11 ========
    local_gates(1);
    bfly(sGp[1][0], 16, (lane>>4)&1, X, Y);
    bfly(sGp[1][1],  8, (lane>>3)&1, X, Y);
    bfly(sGp[1][2],  4, (lane>>2)&1, X, Y);
    bfly(sGp[1][3],  2, (lane>>1)&1, X, Y);
    bfly(sGp[1][4],  1,  lane&1,     X, Y);
    // Pulled layer-3 gates on wires 0,1,2 (masks e_w^e_{w+1}, all lane bits in B)
    {
        bool P0 = (lane>>4)&1;
        bool P1 = __popc(lane & 24) & 1;
        bool P2 = __popc(lane & 28) & 1;
        bfly(sGp[2][0], 24, P0, X, Y);      // wires 0^1 (lane b4^b3)
        bfly(sGp[2][1], 12, P1, X, Y);      // wires 1^2 (lane b3^b2)
        bfly(sGp[2][2],  6, P2, X, Y);      // wires 2^3 (lane b2^b1)
    }

    // ---- Exchange X2: sigma + relayout B->A (pure permutation) ----
    __syncthreads();
    {
        int s0=(lane>>4)&1, s1=(lane>>3)&1, s2=(lane>>2)&1, s3=(lane>>1)&1, s4=lane&1;
        int s5=(warp>>2)&1, s6=(warp>>1)&1, s7=warp&1;
        int mb = (s5^s3) | ((s7^s4)<<1) | (s0<<3)|(s1<<4)|(s2<<5)|(s3<<6)|(s4<<7)|(s6<<8);
        #pragma unroll
        for (int p = 0; p < 8; p++){
            int s8=(p>>2)&1, s9=(p>>1)&1, s10=p&1;
            ex[mb | ((s8^s2)<<2) | (s9<<9)|(s10<<10)] = make_ulonglong2(X[p], Y[p]);
        }
    }
    __syncthreads();
    {
        int d0=(warp>>2)&1, d1=(warp>>1)&1, d2=warp&1;
        int d3=(lane>>4)&1, d4=(lane>>3)&1, d5=(lane>>2)&1, d6=(lane>>1)&1, d7=lane&1;
        int s0=d0, s1=d0^d1, s2=d1^d2, s3=d2^d3, s4=d3^d4, s5=d4^d5, s6=d5^d6, s7=d6^d7;
        int gb = (s5^s3) | ((s7^s4)<<1) | (s0<<3)|(s1<<4)|(s2<<5)|(s3<<6)|(s4<<7)|(s6<<8);
        #pragma unroll
        for (int p = 0; p < 8; p++){
            int d8=(p>>2)&1, d9=(p>>1)&1, d10=p&1;
            int s8=d7^d8, s9=d8^d9, s10=d9^d10;
            ulonglong2 v = ex[gb | ((s8^s2)<<2) | (s9<<9)|(s10<<10)];
            if (p & 1){ X[p] = swap_slots(v.x); Y[p] = swap_slots(v.y); }
            else      { X[p] = v.x;            Y[p] = v.y; }
        }
    }

    // ======== Phase 3 (layout A): layer-3 gates on wires 3-11 ========
    local_gates(2);
    bfly(sGp[2][3], 16, (lane>>4)&1, X, Y);
    bfly(sGp[2][4],  8, (lane>>3)&1, X, Y);
    bfly(sGp[2][5],  4, (lane>>2)&1, X, Y);
    bfly(sGp[2][6],  2, (lane>>1)&1, X, Y);
    bfly(sGp[2][7],  1,  lane&1,     X, Y);

    // ---- Readout: sigma_3 folded via prefix parities.
    int P = 0; float basec = 0.f;
    #pragma unroll
    for (int i = 0; i < 8; i++){
        P ^= (tid >> (7 - i)) & 1;
        basec += P ? -sHw[i] : sHw[i];
    }
    float h8 = sHw[8], h9 = sHw[9], h10 = sHw[10], h11 = sHw[11];
    u64 acc = pk(0.f, 0.f);
    #pragma unroll
    for (int p = 0; p < 8; p++){
        int P8  = P  ^ ((p>>2)&1);
        int P9  = P8 ^ ((p>>1)&1);
        int P10 = P9 ^ (p&1);
        float cp = basec + (P8 ? -h8 : h8) + (P9 ? -h9 : h9) + (P10 ? -h10 : h10);
        float t11 = P10 ? -h11 : h11;
        u64 cpair = pk(cp + t11, cp - t11);
        u64 r2 = f2mul(X[p], X[p]);
        r2 = f2fma(Y[p], Y[p], r2);
        acc = f2fma(cpair, r2, acc);
    }
    float plo, phi; unpk(acc, plo, phi);
    float partial = plo + phi;
    #pragma unroll
    for (int off = 16; off; off >>= 1)
        partial += __shfl_down_sync(FULLMASK, partial, off);
    if (lane == 0) sRed[warp] = partial;
    __syncthreads();
    if (tid == 0){
        float s = hb[0];
        #pragma unroll
        for (int w = 0; w < 8; w++) s += sRed[w];
        out[b] = s;
    }
}

extern "C" void kernel_launch(void* const* d_in, const int* in_sizes, int n_in,
                              void* d_out, int out_size)
{
    const float* x      = (const float*)d_in[0];
    const float* params = (const float*)d_in[1];
    const float* hw     = (const float*)d_in[2];
    const float* hb     = (const float*)d_in[3];
    float* out = (float*)d_out;
    (void)in_sizes; (void)n_in;
    qsim_kernel<<<out_size, 256>>>(x, params, hw, hb, out);
}